// round 1
// baseline (speedup 1.0000x reference)
#include <cuda_runtime.h>
#include <math.h>

// Problem shapes (fixed by the reference)
#define NB 8192          // batch
#define SS 10            // senses
#define HH 1024          // hidden
#define WARPS_PER_BLOCK 8
#define MARGIN_BLOCKS (NB / WARPS_PER_BLOCK)   // 1024
#define ALPHA_ROWS 16200                        // 2700*6
#define ALPHA_BLOCKS 64
#define TOTAL_BLOCKS (MARGIN_BLOCKS + ALPHA_BLOCKS)
#define THREADS 256

// Scratch (device globals: no allocation allowed in kernel_launch)
__device__ float g_margin_part[NB];
__device__ float g_alpha_part[ALPHA_BLOCKS];

__global__ __launch_bounds__(THREADS)
void marginal_loss_main(const float* __restrict__ sentence,
                        const float* __restrict__ gloss,
                        const float* __restrict__ alpha,
                        const int*   __restrict__ mask,
                        const int*   __restrict__ sids)
{
    const int blk = blockIdx.x;

    if (blk < MARGIN_BLOCKS) {
        // ---- margin path: one warp per batch row ----
        const int warp = threadIdx.x >> 5;
        const int lane = threadIdx.x & 31;
        const int b    = blk * WARPS_PER_BLOCK + warp;

        // sentence row -> registers (coalesced float4: lane covers 4 floats,
        // 32 lanes cover 128 floats, 8 steps cover 1024)
        const float4* __restrict__ srow =
            reinterpret_cast<const float4*>(sentence + (size_t)b * HH);
        float4 sv[8];
        #pragma unroll
        for (int j = 0; j < 8; ++j) sv[j] = srow[lane + j * 32];

        // 10 squared distances, single pass over all_gloss[b]
        float acc[SS];
        #pragma unroll
        for (int s = 0; s < SS; ++s) {
            const float4* __restrict__ grow = reinterpret_cast<const float4*>(
                gloss + ((size_t)b * SS + s) * HH);
            float sum = 0.0f;
            #pragma unroll
            for (int j = 0; j < 8; ++j) {
                float4 g = grow[lane + j * 32];
                float d0 = sv[j].x - g.x + 1e-6f;
                float d1 = sv[j].y - g.y + 1e-6f;
                float d2 = sv[j].z - g.z + 1e-6f;
                float d3 = sv[j].w - g.w + 1e-6f;
                sum = fmaf(d0, d0, sum);
                sum = fmaf(d1, d1, sum);
                sum = fmaf(d2, d2, sum);
                sum = fmaf(d3, d3, sum);
            }
            acc[s] = sum;
        }

        // warp reductions (10 independent)
        #pragma unroll
        for (int s = 0; s < SS; ++s) {
            float v = acc[s];
            #pragma unroll
            for (int off = 16; off > 0; off >>= 1)
                v += __shfl_xor_sync(0xffffffffu, v, off);
            acc[s] = v;
        }

        if (lane == 0) {
            const int sid = sids[b];
            float pos  = 0.0f;
            float minv = 1e30f;   // first strict-< win == argmin first-tie rule
            float neg  = 0.0f;
            #pragma unroll
            for (int s = 0; s < SS; ++s) {
                float ds = sqrtf(acc[s]);
                if (s == sid) pos = ds;
                bool valid = (mask[b * SS + s] != 0) && (s != sid);
                float m = valid ? ds : 10.0f;     // SENTINEL
                if (m < minv) { minv = m; neg = ds; }  // carry REAL distance at argmin
            }
            g_margin_part[b] = fmaxf(pos - neg + 0.5f, 0.0f);
        }
    } else {
        // ---- alpha path ----
        const int ab   = blk - MARGIN_BLOCKS;
        const int tid  = ab * THREADS + threadIdx.x;
        const int nthr = ALPHA_BLOCKS * THREADS;
        float part = 0.0f;
        for (int r = tid; r < ALPHA_ROWS; r += nthr) {
            const float* __restrict__ row = alpha + (size_t)r * 10;
            float s0 = 0.0f, mx = -1e30f;
            #pragma unroll
            for (int k = 0; k < 10; ++k) {
                float v = row[k];
                s0 += v;
                mx = fmaxf(mx, v);
            }
            // row_sum==0 -> tmp=ones -> max=1 -> |1-1| = 0
            part += (s0 == 0.0f) ? 0.0f : fabsf(mx - 1.0f);
        }
        __shared__ float sh[THREADS];
        sh[threadIdx.x] = part;
        __syncthreads();
        #pragma unroll
        for (int off = THREADS / 2; off > 0; off >>= 1) {
            if (threadIdx.x < off) sh[threadIdx.x] += sh[threadIdx.x + off];
            __syncthreads();
        }
        if (threadIdx.x == 0) g_alpha_part[ab] = sh[0];
    }
}

__global__ __launch_bounds__(THREADS)
void marginal_loss_finalize(float* __restrict__ out, int out_size)
{
    __shared__ float sh[THREADS];

    // margin sum (deterministic tree reduce)
    float m = 0.0f;
    for (int i = threadIdx.x; i < NB; i += THREADS) m += g_margin_part[i];
    sh[threadIdx.x] = m;
    __syncthreads();
    #pragma unroll
    for (int off = THREADS / 2; off > 0; off >>= 1) {
        if (threadIdx.x < off) sh[threadIdx.x] += sh[threadIdx.x + off];
        __syncthreads();
    }
    float margin = sh[0];
    __syncthreads();

    // alpha sum
    float a = 0.0f;
    for (int i = threadIdx.x; i < ALPHA_BLOCKS; i += THREADS) a += g_alpha_part[i];
    sh[threadIdx.x] = a;
    __syncthreads();
    #pragma unroll
    for (int off = THREADS / 2; off > 0; off >>= 1) {
        if (threadIdx.x < off) sh[threadIdx.x] += sh[threadIdx.x + off];
        __syncthreads();
    }
    float alpha_term = sh[0];

    if (threadIdx.x == 0) {
        float loss = margin * 0.875f + alpha_term * 0.125f;
        out[0] = loss;
        if (out_size > 1) out[1] = margin;
        if (out_size > 2) out[2] = alpha_term;
    }
}

extern "C" void kernel_launch(void* const* d_in, const int* in_sizes, int n_in,
                              void* d_out, int out_size)
{
    // Identify inputs robustly by element count (all distinct):
    //   sentence  8192*1024   = 8388608  (f32)
    //   all_gloss 8192*10*1024= 83886080 (f32)
    //   alpha     2700*6*10   = 162000   (f32)
    //   sense_mask 8192*10    = 81920    (i32)
    //   sense_ids 8192        = 8192     (i32)
    const float* sentence = nullptr;
    const float* gloss    = nullptr;
    const float* alpha    = nullptr;
    const int*   mask     = nullptr;
    const int*   sids     = nullptr;
    for (int i = 0; i < n_in; ++i) {
        switch (in_sizes[i]) {
            case 8388608:  sentence = (const float*)d_in[i]; break;
            case 83886080: gloss    = (const float*)d_in[i]; break;
            case 162000:   alpha    = (const float*)d_in[i]; break;
            case 81920:    mask     = (const int*)  d_in[i]; break;
            case 8192:     sids     = (const int*)  d_in[i]; break;
            default: break;
        }
    }

    marginal_loss_main<<<TOTAL_BLOCKS, THREADS>>>(sentence, gloss, alpha, mask, sids);
    marginal_loss_finalize<<<1, THREADS>>>((float*)d_out, out_size);
}

// round 2
// speedup vs baseline: 1.0567x; 1.0567x over previous
#include <cuda_runtime.h>
#include <math.h>

// Problem shapes (fixed by the reference)
#define NB 8192          // batch
#define SS 10            // senses
#define HH 1024          // hidden
#define THREADS 256
#define NBLOCKS 444      // ~3 blocks x 148 SMs; dynamic tickets make this non-critical
#define ALPHA_ROWS 16200 // 2700*6
#define ALPHA_CHUNKS 64
#define ALPHA_CHUNK 254  // 64*254 = 16256 >= 16200
#define NTICKETS (NB + ALPHA_CHUNKS)

// Scratch (device globals: no allocation allowed anywhere)
__device__ float g_margin_part[NB];
__device__ float g_alpha_part[ALPHA_CHUNKS];
__device__ unsigned int g_ticket;  // zero-init; self-resetting
__device__ unsigned int g_done;    // zero-init; self-resetting

__global__ __launch_bounds__(THREADS)
void marginal_loss_fused(const float* __restrict__ sentence,
                         const float* __restrict__ gloss,
                         const float* __restrict__ alpha,
                         const int*   __restrict__ mask,
                         const int*   __restrict__ sids,
                         float* __restrict__ out, int out_size)
{
    const int warp = threadIdx.x >> 5;
    const int lane = threadIdx.x & 31;
    (void)warp;

    // ---- dynamic ticket loop: perfect balance across SMs ----
    for (;;) {
        unsigned int t;
        if (lane == 0) t = atomicAdd(&g_ticket, 1u);
        t = __shfl_sync(0xffffffffu, t, 0);
        if (t >= NTICKETS) break;

        if (t < NB) {
            // ---- margin row t: one warp computes 10 distances in one pass ----
            const int b = (int)t;
            const float4* __restrict__ srow =
                reinterpret_cast<const float4*>(sentence + (size_t)b * HH);
            float4 sv[8];
            #pragma unroll
            for (int j = 0; j < 8; ++j) sv[j] = srow[lane + j * 32];

            float acc[SS];
            #pragma unroll
            for (int s = 0; s < SS; ++s) {
                const float4* __restrict__ grow = reinterpret_cast<const float4*>(
                    gloss + ((size_t)b * SS + s) * HH);
                float sum = 0.0f;
                #pragma unroll
                for (int j = 0; j < 8; ++j) {
                    float4 g = grow[lane + j * 32];
                    float d0 = sv[j].x - g.x + 1e-6f;
                    float d1 = sv[j].y - g.y + 1e-6f;
                    float d2 = sv[j].z - g.z + 1e-6f;
                    float d3 = sv[j].w - g.w + 1e-6f;
                    sum = fmaf(d0, d0, sum);
                    sum = fmaf(d1, d1, sum);
                    sum = fmaf(d2, d2, sum);
                    sum = fmaf(d3, d3, sum);
                }
                acc[s] = sum;
            }

            #pragma unroll
            for (int s = 0; s < SS; ++s) {
                float v = acc[s];
                #pragma unroll
                for (int off = 16; off > 0; off >>= 1)
                    v += __shfl_xor_sync(0xffffffffu, v, off);
                acc[s] = v;
            }

            if (lane == 0) {
                const int sid = sids[b];
                float pos  = 0.0f;
                float minv = 1e30f;   // first strict-< win == argmin first-index tie rule
                float neg  = 0.0f;
                #pragma unroll
                for (int s = 0; s < SS; ++s) {
                    float ds = sqrtf(acc[s]);
                    if (s == sid) pos = ds;
                    bool valid = (mask[b * SS + s] != 0) && (s != sid);
                    float m = valid ? ds : 10.0f;          // SENTINEL
                    if (m < minv) { minv = m; neg = ds; }  // carry REAL distance at argmin
                }
                g_margin_part[b] = fmaxf(pos - neg + 0.5f, 0.0f);
            }
        } else {
            // ---- alpha chunk ----
            const int c     = (int)(t - NB);
            const int start = c * ALPHA_CHUNK;
            const int end   = min(start + ALPHA_CHUNK, ALPHA_ROWS);
            float part = 0.0f;
            for (int r = start + lane; r < end; r += 32) {
                const float* __restrict__ row = alpha + (size_t)r * 10;
                float s0 = 0.0f, mx = -1e30f;
                #pragma unroll
                for (int k = 0; k < 10; ++k) {
                    float v = row[k];
                    s0 += v;
                    mx = fmaxf(mx, v);
                }
                // row_sum==0 -> tmp=ones -> max=1 -> |1-1| = 0
                part += (s0 == 0.0f) ? 0.0f : fabsf(mx - 1.0f);
            }
            #pragma unroll
            for (int off = 16; off > 0; off >>= 1)
                part += __shfl_xor_sync(0xffffffffu, part, off);
            if (lane == 0) g_alpha_part[c] = part;
        }
    }

    // ---- completion-counter fused finalize (last block only) ----
    __shared__ bool s_last;
    __syncthreads();
    if (threadIdx.x == 0) {
        __threadfence();
        unsigned int d = atomicAdd(&g_done, 1u);
        s_last = (d == (unsigned int)(gridDim.x - 1));
    }
    __syncthreads();
    if (!s_last) return;

    __shared__ float sh[THREADS];

    // margin sum, fixed order -> bit-deterministic
    float m = 0.0f;
    for (int i = threadIdx.x; i < NB; i += THREADS) m += g_margin_part[i];
    sh[threadIdx.x] = m;
    __syncthreads();
    #pragma unroll
    for (int off = THREADS / 2; off > 0; off >>= 1) {
        if (threadIdx.x < off) sh[threadIdx.x] += sh[threadIdx.x + off];
        __syncthreads();
    }
    float margin = sh[0];
    __syncthreads();

    // alpha sum
    float a = (threadIdx.x < ALPHA_CHUNKS) ? g_alpha_part[threadIdx.x] : 0.0f;
    sh[threadIdx.x] = a;
    __syncthreads();
    #pragma unroll
    for (int off = THREADS / 2; off > 0; off >>= 1) {
        if (threadIdx.x < off) sh[threadIdx.x] += sh[threadIdx.x + off];
        __syncthreads();
    }
    float alpha_term = sh[0];

    if (threadIdx.x == 0) {
        float loss = margin * 0.875f + alpha_term * 0.125f;
        out[0] = loss;
        if (out_size > 1) out[1] = margin;
        if (out_size > 2) out[2] = alpha_term;
        // self-reset for next graph replay (stream order guarantees visibility)
        g_ticket = 0u;
        g_done   = 0u;
    }
}

extern "C" void kernel_launch(void* const* d_in, const int* in_sizes, int n_in,
                              void* d_out, int out_size)
{
    // Identify inputs robustly by element count (all distinct):
    //   sentence  8192*1024    = 8388608  (f32)
    //   all_gloss 8192*10*1024 = 83886080 (f32)
    //   alpha     2700*6*10    = 162000   (f32)
    //   sense_mask 8192*10     = 81920    (i32)
    //   sense_ids 8192         = 8192     (i32)
    const float* sentence = nullptr;
    const float* gloss    = nullptr;
    const float* alpha    = nullptr;
    const int*   mask     = nullptr;
    const int*   sids     = nullptr;
    for (int i = 0; i < n_in; ++i) {
        switch (in_sizes[i]) {
            case 8388608:  sentence = (const float*)d_in[i]; break;
            case 83886080: gloss    = (const float*)d_in[i]; break;
            case 162000:   alpha    = (const float*)d_in[i]; break;
            case 81920:    mask     = (const int*)  d_in[i]; break;
            case 8192:     sids     = (const int*)  d_in[i]; break;
            default: break;
        }
    }

    marginal_loss_fused<<<NBLOCKS, THREADS>>>(sentence, gloss, alpha, mask, sids,
                                              (float*)d_out, out_size);
}